// round 2
// baseline (speedup 1.0000x reference)
#include <cuda_runtime.h>
#include <cuda_bf16.h>
#include <math.h>

// VectorQuantizer: inputs [16,4096,64] f32, weight [1024,64] f32.
// Output layout (f32): [loss(1) | quantized_ste(65536*64) | perplexity(1) | indices(65536)]
// NOTE: out + 1 is only 4-byte aligned -> all stores into out_q must be scalar.

#define N_TOK   65536
#define DIM     64
#define NCODE   1024
#define CHUNK   128          // codes staged in smem per iteration
#define TPB     128          // tokens per block (1 token/thread)
#define NBLK    (N_TOK / TPB)   // 512

__device__ __align__(16) float g_wnorm[NCODE * DIM];
__device__ float g_wsq[NCODE];
__device__ int   g_counts[NCODE];
__device__ float g_partials[NBLK];

#define FFMA2(acc, a, b) \
    asm("fma.rn.f32x2 %0, %1, %2, %0;" : "+l"(acc) : "l"(a), "l"(b))

__device__ __forceinline__ float f32x2_hsum(unsigned long long v) {
    float lo, hi;
    asm("mov.b64 {%0,%1}, %2;" : "=f"(lo), "=f"(hi) : "l"(v));
    return lo + hi;
}

// ---------------------------------------------------------------------------
// Kernel 0: zero the histogram (graph replays must be idempotent)
// ---------------------------------------------------------------------------
__global__ void vq_init() {
    int i = blockIdx.x * blockDim.x + threadIdx.x;
    if (i < NCODE) g_counts[i] = 0;
}

// ---------------------------------------------------------------------------
// Kernel 1: normalize codebook rows, record per-row squared norm (post-norm)
// ---------------------------------------------------------------------------
__global__ __launch_bounds__(128) void vq_wnorm(const float* __restrict__ w) {
    int r = blockIdx.x * 128 + threadIdx.x;   // 8 blocks x 128 = 1024 rows
    if (r >= NCODE) return;
    const float4* src = reinterpret_cast<const float4*>(w + (size_t)r * DIM);
    float v[DIM];
    float ss = 0.f;
#pragma unroll
    for (int i = 0; i < DIM / 4; i++) {
        float4 q = src[i];
        v[4*i+0] = q.x; v[4*i+1] = q.y; v[4*i+2] = q.z; v[4*i+3] = q.w;
        ss += q.x*q.x + q.y*q.y + q.z*q.z + q.w*q.w;
    }
    float inv = 1.0f / fmaxf(sqrtf(ss), 1e-12f);
    float sq = 0.f;
    float4* dst = reinterpret_cast<float4*>(g_wnorm + (size_t)r * DIM);
#pragma unroll
    for (int i = 0; i < DIM / 4; i++) {
        float4 q;
        q.x = v[4*i+0] * inv; q.y = v[4*i+1] * inv;
        q.z = v[4*i+2] * inv; q.w = v[4*i+3] * inv;
        sq += q.x*q.x + q.y*q.y + q.z*q.z + q.w*q.w;
        dst[i] = q;
    }
    g_wsq[r] = sq;
}

// ---------------------------------------------------------------------------
// Kernel 2: main — normalize token, argmin over codes, write quantized+index,
//           per-block deterministic loss partial, histogram (int atomics).
// ---------------------------------------------------------------------------
__global__ __launch_bounds__(TPB) void vq_main(const float* __restrict__ x_in,
                                               float* __restrict__ out_q,
                                               float* __restrict__ out_idx) {
    __shared__ __align__(16) float sh[CHUNK * DIM];   // 32 KB
    __shared__ float shwsq[CHUNK];
    __shared__ float red[TPB];

    const int tid = threadIdx.x;
    const int t   = blockIdx.x * TPB + tid;           // token id, always < N_TOK

    // --- load + normalize token into registers ---
    const float4* xin4 = reinterpret_cast<const float4*>(x_in + (size_t)t * DIM);
    float xr[DIM];
    float ss = 0.f;
#pragma unroll
    for (int i = 0; i < DIM / 4; i++) {
        float4 q = xin4[i];
        xr[4*i+0] = q.x; xr[4*i+1] = q.y; xr[4*i+2] = q.z; xr[4*i+3] = q.w;
        ss += q.x*q.x + q.y*q.y + q.z*q.z + q.w*q.w;
    }
    float inv = 1.0f / fmaxf(sqrtf(ss), 1e-12f);
    float xsq = 0.f;
#pragma unroll
    for (int i = 0; i < DIM; i++) { xr[i] *= inv; xsq += xr[i] * xr[i]; }

    // pack into f32x2 pairs
    unsigned long long xp[DIM / 2];
#pragma unroll
    for (int i = 0; i < DIM / 2; i++)
        asm("mov.b64 %0, {%1,%2};" : "=l"(xp[i]) : "f"(xr[2*i]), "f"(xr[2*i+1]));

    float bestd = INFINITY;
    int   besti = 0;

    for (int c0 = 0; c0 < NCODE; c0 += CHUNK) {
        __syncthreads();   // previous chunk's readers done before overwrite
        {
            const float4* src = reinterpret_cast<const float4*>(g_wnorm + (size_t)c0 * DIM);
            float4* dst = reinterpret_cast<float4*>(sh);
#pragma unroll
            for (int i = 0; i < (CHUNK * DIM / 4) / TPB; i++)   // 16 iters
                dst[i * TPB + tid] = src[i * TPB + tid];
            shwsq[tid] = g_wsq[c0 + tid];   // TPB == CHUNK
        }
        __syncthreads();

        for (int kk = 0; kk < CHUNK; kk += 4) {
            const ulonglong2* w0 = reinterpret_cast<const ulonglong2*>(sh + (kk + 0) * DIM);
            const ulonglong2* w1 = reinterpret_cast<const ulonglong2*>(sh + (kk + 1) * DIM);
            const ulonglong2* w2 = reinterpret_cast<const ulonglong2*>(sh + (kk + 2) * DIM);
            const ulonglong2* w3 = reinterpret_cast<const ulonglong2*>(sh + (kk + 3) * DIM);
            unsigned long long a0 = 0ull, a1 = 0ull, a2 = 0ull, a3 = 0ull;
#pragma unroll
            for (int j = 0; j < DIM / 4; j++) {   // 16 iters, 2 f32x2 per code each
                ulonglong2 v0 = w0[j], v1 = w1[j], v2 = w2[j], v3 = w3[j];
                FFMA2(a0, xp[2*j],   v0.x);
                FFMA2(a1, xp[2*j],   v1.x);
                FFMA2(a2, xp[2*j],   v2.x);
                FFMA2(a3, xp[2*j],   v3.x);
                FFMA2(a0, xp[2*j+1], v0.y);
                FFMA2(a1, xp[2*j+1], v1.y);
                FFMA2(a2, xp[2*j+1], v2.y);
                FFMA2(a3, xp[2*j+1], v3.y);
            }
            float d0 = f32x2_hsum(a0);
            float d1 = f32x2_hsum(a1);
            float d2 = f32x2_hsum(a2);
            float d3 = f32x2_hsum(a3);
            float s0 = fmaf(-2.0f, d0, shwsq[kk + 0]);
            float s1 = fmaf(-2.0f, d1, shwsq[kk + 1]);
            float s2 = fmaf(-2.0f, d2, shwsq[kk + 2]);
            float s3 = fmaf(-2.0f, d3, shwsq[kk + 3]);
            // strict < in ascending k order == jnp.argmin first-min tiebreak
            if (s0 < bestd) { bestd = s0; besti = c0 + kk + 0; }
            if (s1 < bestd) { bestd = s1; besti = c0 + kk + 1; }
            if (s2 < bestd) { bestd = s2; besti = c0 + kk + 2; }
            if (s3 < bestd) { bestd = s3; besti = c0 + kk + 3; }
        }
    }

    // --- outputs ---
    // out_q is 4-byte aligned only (out + 1): scalar stores required.
    {
        const float* wb = g_wnorm + (size_t)besti * DIM;
        float* qo = out_q + (size_t)t * DIM;
#pragma unroll
        for (int i = 0; i < DIM; i++) qo[i] = wb[i];
    }
    out_idx[t] = (float)besti;
    atomicAdd(&g_counts[besti], 1);

    // per-token loss contribution: ||q - x||^2 = xsq + (wsq - 2*dot) = xsq + bestd
    __syncthreads();
    red[tid] = xsq + bestd;
    __syncthreads();
#pragma unroll
    for (int s = TPB / 2; s > 0; s >>= 1) {
        if (tid < s) red[tid] += red[tid + s];
        __syncthreads();
    }
    if (tid == 0) g_partials[blockIdx.x] = red[0];
}

// ---------------------------------------------------------------------------
// Kernel 3: finalize — perplexity from histogram, loss from block partials.
// Single block, fixed-order tree reductions => deterministic.
// ---------------------------------------------------------------------------
__global__ __launch_bounds__(1024) void vq_finalize(float* __restrict__ out_loss,
                                                    float* __restrict__ out_perp) {
    __shared__ float red[1024];
    int i = threadIdx.x;

    // entropy
    float p = (float)g_counts[i] * (1.0f / (float)N_TOK);
    red[i] = p * logf(p + 1e-10f);
    __syncthreads();
#pragma unroll
    for (int s = 512; s > 0; s >>= 1) {
        if (i < s) red[i] += red[i + s];
        __syncthreads();
    }
    if (i == 0) *out_perp = expf(-red[0]);
    __syncthreads();

    // loss
    red[i] = (i < NBLK) ? g_partials[i] : 0.0f;
    __syncthreads();
#pragma unroll
    for (int s = 512; s > 0; s >>= 1) {
        if (i < s) red[i] += red[i + s];
        __syncthreads();
    }
    if (i == 0)
        *out_loss = (1.0f + 0.25f) * (red[0] / (float)((long long)N_TOK * DIM));
}

// ---------------------------------------------------------------------------
extern "C" void kernel_launch(void* const* d_in, const int* in_sizes, int n_in,
                              void* d_out, int out_size) {
    // inputs: [0]=inputs (4194304 elems), [1]=weight (65536 elems); guard by size
    const float* x = (const float*)d_in[0];
    const float* w = (const float*)d_in[1];
    if (n_in >= 2 && in_sizes[0] < in_sizes[1]) {
        x = (const float*)d_in[1];
        w = (const float*)d_in[0];
    }

    float* out = (float*)d_out;
    const long long ND = (long long)N_TOK * DIM;
    float* out_loss = out;             // [0]
    float* out_q    = out + 1;         // [1, 1+ND)
    float* out_perp = out + 1 + ND;    // [1+ND]
    float* out_idx  = out + 2 + ND;    // [2+ND, 2+ND+N_TOK)

    vq_init<<<4, 256>>>();
    vq_wnorm<<<8, 128>>>(w);
    vq_main<<<NBLK, TPB>>>(x, out_q, out_idx);
    vq_finalize<<<1, 1024>>>(out_loss, out_perp);
}

// round 3
// speedup vs baseline: 1.0025x; 1.0025x over previous
#include <cuda_runtime.h>
#include <cuda_bf16.h>
#include <math.h>

// VectorQuantizer: inputs [16,4096,64] f32, weight [1024,64] f32.
// Output layout (f32): [loss(1) | quantized_ste(65536*64) | perplexity(1) | indices(65536)]
// NOTE: out + 1 is only 4-byte aligned -> all stores into out_q must be scalar.

#define N_TOK   65536
#define DIM     64
#define NCODE   1024
#define CHUNK   128          // codes staged in smem per iteration
#define TPB     128          // tokens per block (1 token/thread)
#define NBLK    (N_TOK / TPB)   // 512

__device__ __align__(16) float g_wnorm[NCODE * DIM];
__device__ float g_wsq[NCODE];
__device__ int   g_counts[NCODE];
__device__ float g_partials[NBLK];

#define FFMA2(acc, a, b) \
    asm("fma.rn.f32x2 %0, %1, %2, %0;" : "+l"(acc) : "l"(a), "l"(b))
#define MUL2(d, a, b) \
    asm("mul.rn.f32x2 %0, %1, %2;" : "=l"(d) : "l"(a), "l"(b))
#define PACK2(d, lo, hi) \
    asm("mov.b64 %0, {%1,%2};" : "=l"(d) : "f"(lo), "f"(hi))

__device__ __forceinline__ float f32x2_hsum(unsigned long long v) {
    float lo, hi;
    asm("mov.b64 {%0,%1}, %2;" : "=f"(lo), "=f"(hi) : "l"(v));
    return lo + hi;
}

// ---------------------------------------------------------------------------
// Kernel 0: zero the histogram (graph replays must be idempotent)
// ---------------------------------------------------------------------------
__global__ void vq_init() {
    int i = blockIdx.x * blockDim.x + threadIdx.x;
    if (i < NCODE) g_counts[i] = 0;
}

// ---------------------------------------------------------------------------
// Kernel 1: normalize codebook rows, record per-row squared norm (post-norm)
// ---------------------------------------------------------------------------
__global__ __launch_bounds__(128) void vq_wnorm(const float* __restrict__ w) {
    int r = blockIdx.x * 128 + threadIdx.x;   // 8 blocks x 128 = 1024 rows
    if (r >= NCODE) return;
    const float4* src = reinterpret_cast<const float4*>(w + (size_t)r * DIM);
    float v[DIM];
    float ss = 0.f;
#pragma unroll
    for (int i = 0; i < DIM / 4; i++) {
        float4 q = src[i];
        v[4*i+0] = q.x; v[4*i+1] = q.y; v[4*i+2] = q.z; v[4*i+3] = q.w;
        ss += q.x*q.x + q.y*q.y + q.z*q.z + q.w*q.w;
    }
    float inv = 1.0f / fmaxf(sqrtf(ss), 1e-12f);
    float sq = 0.f;
    float4* dst = reinterpret_cast<float4*>(g_wnorm + (size_t)r * DIM);
#pragma unroll
    for (int i = 0; i < DIM / 4; i++) {
        float4 q;
        q.x = v[4*i+0] * inv; q.y = v[4*i+1] * inv;
        q.z = v[4*i+2] * inv; q.w = v[4*i+3] * inv;
        sq += q.x*q.x + q.y*q.y + q.z*q.z + q.w*q.w;
        dst[i] = q;
    }
    g_wsq[r] = sq;
}

// ---------------------------------------------------------------------------
// Kernel 2: main — normalize token, argmin over codes, write quantized+index,
//           per-block deterministic loss partial, histogram (int atomics).
// Register budget is the whole game here: x lives ONLY as 32 packed f32x2
// (64 regs); never materialize a separate float[64] copy.
// ---------------------------------------------------------------------------
__global__ __launch_bounds__(TPB, 4) void vq_main(const float* __restrict__ x_in,
                                                  float* __restrict__ out_q,
                                                  float* __restrict__ out_idx) {
    __shared__ __align__(16) float sh[CHUNK * DIM];   // 32 KB
    __shared__ float shwsq[CHUNK];
    __shared__ float red[TPB];

    const int tid = threadIdx.x;
    const int t   = blockIdx.x * TPB + tid;           // token id, always < N_TOK

    // --- load token, pack directly into f32x2 pairs, accumulate sum-sq ---
    const float4* xin4 = reinterpret_cast<const float4*>(x_in + (size_t)t * DIM);
    unsigned long long xp[DIM / 2];
    float ss = 0.f;
#pragma unroll
    for (int i = 0; i < DIM / 4; i++) {
        float4 q = xin4[i];
        ss = fmaf(q.x, q.x, ss); ss = fmaf(q.y, q.y, ss);
        ss = fmaf(q.z, q.z, ss); ss = fmaf(q.w, q.w, ss);
        PACK2(xp[2*i],   q.x, q.y);
        PACK2(xp[2*i+1], q.z, q.w);
    }
    float inv = 1.0f / fmaxf(sqrtf(ss), 1e-12f);
    unsigned long long invp;
    PACK2(invp, inv, inv);
    unsigned long long sacc = 0ull;
#pragma unroll
    for (int i = 0; i < DIM / 2; i++) {
        MUL2(xp[i], xp[i], invp);
        FFMA2(sacc, xp[i], xp[i]);
    }
    const float xsq = f32x2_hsum(sacc);

    float bestd = INFINITY;
    int   besti = 0;

    for (int c0 = 0; c0 < NCODE; c0 += CHUNK) {
        __syncthreads();   // previous chunk's readers done before overwrite
        {
            const float4* src = reinterpret_cast<const float4*>(g_wnorm + (size_t)c0 * DIM);
            float4* dst = reinterpret_cast<float4*>(sh);
#pragma unroll
            for (int i = 0; i < (CHUNK * DIM / 4) / TPB; i++)   // 16 iters
                dst[i * TPB + tid] = src[i * TPB + tid];
            shwsq[tid] = g_wsq[c0 + tid];   // TPB == CHUNK
        }
        __syncthreads();

        for (int kk = 0; kk < CHUNK; kk += 4) {
            // one base pointer, immediate offsets (row = 16 ulonglong2)
            const ulonglong2* wb = reinterpret_cast<const ulonglong2*>(sh + kk * DIM);
            unsigned long long a0 = 0ull, a1 = 0ull, a2 = 0ull, a3 = 0ull;
#pragma unroll
            for (int j = 0; j < DIM / 4; j++) {   // 16 iters
                ulonglong2 v0 = wb[j];
                ulonglong2 v1 = wb[16 + j];
                ulonglong2 v2 = wb[32 + j];
                ulonglong2 v3 = wb[48 + j];
                FFMA2(a0, xp[2*j],   v0.x);
                FFMA2(a1, xp[2*j],   v1.x);
                FFMA2(a2, xp[2*j],   v2.x);
                FFMA2(a3, xp[2*j],   v3.x);
                FFMA2(a0, xp[2*j+1], v0.y);
                FFMA2(a1, xp[2*j+1], v1.y);
                FFMA2(a2, xp[2*j+1], v2.y);
                FFMA2(a3, xp[2*j+1], v3.y);
            }
            float d0 = f32x2_hsum(a0);
            float d1 = f32x2_hsum(a1);
            float d2 = f32x2_hsum(a2);
            float d3 = f32x2_hsum(a3);
            float s0 = fmaf(-2.0f, d0, shwsq[kk + 0]);
            float s1 = fmaf(-2.0f, d1, shwsq[kk + 1]);
            float s2 = fmaf(-2.0f, d2, shwsq[kk + 2]);
            float s3 = fmaf(-2.0f, d3, shwsq[kk + 3]);
            // strict < in ascending k order == jnp.argmin first-min tiebreak
            if (s0 < bestd) { bestd = s0; besti = c0 + kk + 0; }
            if (s1 < bestd) { bestd = s1; besti = c0 + kk + 1; }
            if (s2 < bestd) { bestd = s2; besti = c0 + kk + 2; }
            if (s3 < bestd) { bestd = s3; besti = c0 + kk + 3; }
        }
    }

    // --- outputs ---
    // out_q is 4-byte aligned only (out + 1): scalar stores required.
    {
        const float* wbq = g_wnorm + (size_t)besti * DIM;
        float* qo = out_q + (size_t)t * DIM;
#pragma unroll
        for (int i = 0; i < DIM; i++) qo[i] = wbq[i];
    }
    out_idx[t] = (float)besti;
    atomicAdd(&g_counts[besti], 1);

    // per-token loss contribution: ||q - x||^2 = xsq + (wsq - 2*dot) = xsq + bestd
    __syncthreads();
    red[tid] = xsq + bestd;
    __syncthreads();
#pragma unroll
    for (int s = TPB / 2; s > 0; s >>= 1) {
        if (tid < s) red[tid] += red[tid + s];
        __syncthreads();
    }
    if (tid == 0) g_partials[blockIdx.x] = red[0];
}

// ---------------------------------------------------------------------------
// Kernel 3: finalize — perplexity from histogram, loss from block partials.
// Single block, fixed-order tree reductions => deterministic.
// ---------------------------------------------------------------------------
__global__ __launch_bounds__(1024) void vq_finalize(float* __restrict__ out_loss,
                                                    float* __restrict__ out_perp) {
    __shared__ float red[1024];
    int i = threadIdx.x;

    // entropy
    float p = (float)g_counts[i] * (1.0f / (float)N_TOK);
    red[i] = p * logf(p + 1e-10f);
    __syncthreads();
#pragma unroll
    for (int s = 512; s > 0; s >>= 1) {
        if (i < s) red[i] += red[i + s];
        __syncthreads();
    }
    if (i == 0) *out_perp = expf(-red[0]);
    __syncthreads();

    // loss
    red[i] = (i < NBLK) ? g_partials[i] : 0.0f;
    __syncthreads();
#pragma unroll
    for (int s = 512; s > 0; s >>= 1) {
        if (i < s) red[i] += red[i + s];
        __syncthreads();
    }
    if (i == 0)
        *out_loss = (1.0f + 0.25f) * (red[0] / (float)((long long)N_TOK * DIM));
}

// ---------------------------------------------------------------------------
extern "C" void kernel_launch(void* const* d_in, const int* in_sizes, int n_in,
                              void* d_out, int out_size) {
    // inputs: [0]=inputs (4194304 elems), [1]=weight (65536 elems); guard by size
    const float* x = (const float*)d_in[0];
    const float* w = (const float*)d_in[1];
    if (n_in >= 2 && in_sizes[0] < in_sizes[1]) {
        x = (const float*)d_in[1];
        w = (const float*)d_in[0];
    }

    float* out = (float*)d_out;
    const long long ND = (long long)N_TOK * DIM;
    float* out_loss = out;             // [0]
    float* out_q    = out + 1;         // [1, 1+ND)
    float* out_perp = out + 1 + ND;    // [1+ND]
    float* out_idx  = out + 2 + ND;    // [2+ND, 2+ND+N_TOK)

    vq_init<<<4, 256>>>();
    vq_wnorm<<<8, 128>>>(w);
    vq_main<<<NBLK, TPB>>>(x, out_q, out_idx);
    vq_finalize<<<1, 1024>>>(out_loss, out_perp);
}

// round 4
// speedup vs baseline: 1.3740x; 1.3705x over previous
#include <cuda_runtime.h>
#include <cuda_bf16.h>
#include <math.h>

// VectorQuantizer: inputs [16,4096,64] f32, weight [1024,64] f32.
// Output layout (f32): [loss(1) | quantized_ste(65536*64) | perplexity(1) | indices(65536)]
// out+1 is only 4-byte aligned -> scalar stores into out_q.

#define N_TOK   65536
#define DIM     64
#define NCODE   1024
#define CHUNK   128
#define TPB     128
#define TT      2                       // tokens per thread
#define TOK_PER_BLK (TPB * TT)          // 256
#define NBLK    (N_TOK / TOK_PER_BLK)   // 256

__device__ __align__(16) float g_wnorm[NCODE * DIM];
__device__ float g_wsq[NCODE];
__device__ int   g_counts[NCODE];
__device__ float g_partials[NBLK];
__device__ unsigned g_done;

#define FFMA2(acc, a, b) \
    asm("fma.rn.f32x2 %0, %1, %2, %0;" : "+l"(acc) : "l"(a), "l"(b))
#define MUL2(d, a, b) \
    asm("mul.rn.f32x2 %0, %1, %2;" : "=l"(d) : "l"(a), "l"(b))
#define PACK2(d, lo, hi) \
    asm("mov.b64 %0, {%1,%2};" : "=l"(d) : "f"(lo), "f"(hi))

__device__ __forceinline__ float f32x2_hsum(unsigned long long v) {
    float lo, hi;
    asm("mov.b64 {%0,%1}, %2;" : "=f"(lo), "=f"(hi) : "l"(v));
    return lo + hi;
}

// ---------------------------------------------------------------------------
// Kernel 1: prep — zero histogram + done counter, normalize codebook rows.
// ---------------------------------------------------------------------------
__global__ __launch_bounds__(128) void vq_prep(const float* __restrict__ w) {
    int r = blockIdx.x * 128 + threadIdx.x;   // 8 x 128 = 1024 rows
    if (r == 0) g_done = 0;
    if (r >= NCODE) return;
    g_counts[r] = 0;
    const float4* src = reinterpret_cast<const float4*>(w + (size_t)r * DIM);
    float v[DIM];
    float ss = 0.f;
#pragma unroll
    for (int i = 0; i < DIM / 4; i++) {
        float4 q = src[i];
        v[4*i+0] = q.x; v[4*i+1] = q.y; v[4*i+2] = q.z; v[4*i+3] = q.w;
        ss += q.x*q.x + q.y*q.y + q.z*q.z + q.w*q.w;
    }
    float inv = 1.0f / fmaxf(sqrtf(ss), 1e-12f);
    float sq = 0.f;
    float4* dst = reinterpret_cast<float4*>(g_wnorm + (size_t)r * DIM);
#pragma unroll
    for (int i = 0; i < DIM / 4; i++) {
        float4 q;
        q.x = v[4*i+0] * inv; q.y = v[4*i+1] * inv;
        q.z = v[4*i+2] * inv; q.w = v[4*i+3] * inv;
        sq += q.x*q.x + q.y*q.y + q.z*q.z + q.w*q.w;
        dst[i] = q;
    }
    g_wsq[r] = sq;
}

// ---------------------------------------------------------------------------
// Kernel 2: main — 2 tokens/thread (w loads amortized over both), argmin,
// outputs, per-block loss partial, histogram; LAST block finalizes loss+perp.
// ---------------------------------------------------------------------------
__global__ __launch_bounds__(TPB, 2) void vq_main(const float* __restrict__ x_in,
                                                  float* __restrict__ out_q,
                                                  float* __restrict__ out_idx,
                                                  float* __restrict__ out_loss,
                                                  float* __restrict__ out_perp) {
    __shared__ __align__(16) float sh[CHUNK * DIM];   // 32 KB
    __shared__ float shwsq[CHUNK];
    __shared__ float red[TPB];
    __shared__ bool  is_last;

    const int tid = threadIdx.x;
    const int t0  = blockIdx.x * TOK_PER_BLK + tid;
    const int t1  = t0 + TPB;

    // --- load + normalize both tokens, packed f32x2 only ---
    unsigned long long xp0[DIM / 2], xp1[DIM / 2];
    float xsq0, xsq1;
    {
        const float4* a4 = reinterpret_cast<const float4*>(x_in + (size_t)t0 * DIM);
        const float4* b4 = reinterpret_cast<const float4*>(x_in + (size_t)t1 * DIM);
        float ssa = 0.f, ssb = 0.f;
#pragma unroll
        for (int i = 0; i < DIM / 4; i++) {
            float4 q = a4[i];
            ssa = fmaf(q.x, q.x, ssa); ssa = fmaf(q.y, q.y, ssa);
            ssa = fmaf(q.z, q.z, ssa); ssa = fmaf(q.w, q.w, ssa);
            PACK2(xp0[2*i],   q.x, q.y);
            PACK2(xp0[2*i+1], q.z, q.w);
            float4 r = b4[i];
            ssb = fmaf(r.x, r.x, ssb); ssb = fmaf(r.y, r.y, ssb);
            ssb = fmaf(r.z, r.z, ssb); ssb = fmaf(r.w, r.w, ssb);
            PACK2(xp1[2*i],   r.x, r.y);
            PACK2(xp1[2*i+1], r.z, r.w);
        }
        float inva = 1.0f / fmaxf(sqrtf(ssa), 1e-12f);
        float invb = 1.0f / fmaxf(sqrtf(ssb), 1e-12f);
        unsigned long long ia, ib, sa = 0ull, sb = 0ull;
        PACK2(ia, inva, inva);
        PACK2(ib, invb, invb);
#pragma unroll
        for (int i = 0; i < DIM / 2; i++) {
            MUL2(xp0[i], xp0[i], ia);
            FFMA2(sa, xp0[i], xp0[i]);
            MUL2(xp1[i], xp1[i], ib);
            FFMA2(sb, xp1[i], xp1[i]);
        }
        xsq0 = f32x2_hsum(sa);
        xsq1 = f32x2_hsum(sb);
    }

    float bd0 = INFINITY, bd1 = INFINITY;
    int   bi0 = 0,        bi1 = 0;

    for (int c0 = 0; c0 < NCODE; c0 += CHUNK) {
        __syncthreads();
        {
            const float4* src = reinterpret_cast<const float4*>(g_wnorm + (size_t)c0 * DIM);
            float4* dst = reinterpret_cast<float4*>(sh);
#pragma unroll
            for (int i = 0; i < (CHUNK * DIM / 4) / TPB; i++)   // 16
                dst[i * TPB + tid] = src[i * TPB + tid];
            shwsq[tid] = g_wsq[c0 + tid];
        }
        __syncthreads();

        for (int kk = 0; kk < CHUNK; kk += 4) {
            const ulonglong2* wb = reinterpret_cast<const ulonglong2*>(sh + kk * DIM);
            unsigned long long a00 = 0ull, a01 = 0ull, a02 = 0ull, a03 = 0ull;
            unsigned long long a10 = 0ull, a11 = 0ull, a12 = 0ull, a13 = 0ull;
#pragma unroll
            for (int j = 0; j < DIM / 4; j++) {   // 16: 4 LDS.128 feed 16 FFMA2
                ulonglong2 v0 = wb[j];
                ulonglong2 v1 = wb[16 + j];
                ulonglong2 v2 = wb[32 + j];
                ulonglong2 v3 = wb[48 + j];
                FFMA2(a00, xp0[2*j],   v0.x); FFMA2(a10, xp1[2*j],   v0.x);
                FFMA2(a01, xp0[2*j],   v1.x); FFMA2(a11, xp1[2*j],   v1.x);
                FFMA2(a02, xp0[2*j],   v2.x); FFMA2(a12, xp1[2*j],   v2.x);
                FFMA2(a03, xp0[2*j],   v3.x); FFMA2(a13, xp1[2*j],   v3.x);
                FFMA2(a00, xp0[2*j+1], v0.y); FFMA2(a10, xp1[2*j+1], v0.y);
                FFMA2(a01, xp0[2*j+1], v1.y); FFMA2(a11, xp1[2*j+1], v1.y);
                FFMA2(a02, xp0[2*j+1], v2.y); FFMA2(a12, xp1[2*j+1], v2.y);
                FFMA2(a03, xp0[2*j+1], v3.y); FFMA2(a13, xp1[2*j+1], v3.y);
            }
            float w0 = shwsq[kk+0], w1 = shwsq[kk+1], w2 = shwsq[kk+2], w3 = shwsq[kk+3];
            float s00 = fmaf(-2.0f, f32x2_hsum(a00), w0);
            float s01 = fmaf(-2.0f, f32x2_hsum(a01), w1);
            float s02 = fmaf(-2.0f, f32x2_hsum(a02), w2);
            float s03 = fmaf(-2.0f, f32x2_hsum(a03), w3);
            float s10 = fmaf(-2.0f, f32x2_hsum(a10), w0);
            float s11 = fmaf(-2.0f, f32x2_hsum(a11), w1);
            float s12 = fmaf(-2.0f, f32x2_hsum(a12), w2);
            float s13 = fmaf(-2.0f, f32x2_hsum(a13), w3);
            // strict < ascending == jnp.argmin first-min tiebreak
            if (s00 < bd0) { bd0 = s00; bi0 = c0 + kk + 0; }
            if (s01 < bd0) { bd0 = s01; bi0 = c0 + kk + 1; }
            if (s02 < bd0) { bd0 = s02; bi0 = c0 + kk + 2; }
            if (s03 < bd0) { bd0 = s03; bi0 = c0 + kk + 3; }
            if (s10 < bd1) { bd1 = s10; bi1 = c0 + kk + 0; }
            if (s11 < bd1) { bd1 = s11; bi1 = c0 + kk + 1; }
            if (s12 < bd1) { bd1 = s12; bi1 = c0 + kk + 2; }
            if (s13 < bd1) { bd1 = s13; bi1 = c0 + kk + 3; }
        }
    }

    // --- outputs (scalar stores: out_q only 4B-aligned) ---
    {
        const float* wq0 = g_wnorm + (size_t)bi0 * DIM;
        float* qo0 = out_q + (size_t)t0 * DIM;
        const float* wq1 = g_wnorm + (size_t)bi1 * DIM;
        float* qo1 = out_q + (size_t)t1 * DIM;
#pragma unroll
        for (int i = 0; i < DIM; i++) { qo0[i] = wq0[i]; qo1[i] = wq1[i]; }
    }
    out_idx[t0] = (float)bi0;
    out_idx[t1] = (float)bi1;
    atomicAdd(&g_counts[bi0], 1);
    atomicAdd(&g_counts[bi1], 1);

    // --- per-block deterministic loss partial ---
    __syncthreads();
    red[tid] = (xsq0 + bd0) + (xsq1 + bd1);
    __syncthreads();
#pragma unroll
    for (int s = TPB / 2; s > 0; s >>= 1) {
        if (tid < s) red[tid] += red[tid + s];
        __syncthreads();
    }
    if (tid == 0) {
        g_partials[blockIdx.x] = red[0];
        __threadfence();
        unsigned v = atomicAdd(&g_done, 1u);
        is_last = (v == NBLK - 1);
    }
    __syncthreads();

    // --- last block finalizes loss + perplexity (fixed-order => deterministic) ---
    if (is_last) {
        __threadfence();
        // entropy: 8 counts per thread, then block tree
        float e = 0.f;
#pragma unroll
        for (int j = 0; j < NCODE / TPB; j++) {
            int c = __ldcg(&g_counts[tid * (NCODE / TPB) + j]);
            float p = (float)c * (1.0f / (float)N_TOK);
            e += p * logf(p + 1e-10f);
        }
        red[tid] = e;
        __syncthreads();
#pragma unroll
        for (int s = TPB / 2; s > 0; s >>= 1) {
            if (tid < s) red[tid] += red[tid + s];
            __syncthreads();
        }
        if (tid == 0) *out_perp = expf(-red[0]);
        __syncthreads();

        // loss: NBLK=256 partials, 2 per thread, then block tree
        float l = __ldcg(&g_partials[tid]) + __ldcg(&g_partials[tid + TPB]);
        red[tid] = l;
        __syncthreads();
#pragma unroll
        for (int s = TPB / 2; s > 0; s >>= 1) {
            if (tid < s) red[tid] += red[tid + s];
            __syncthreads();
        }
        if (tid == 0)
            *out_loss = 1.25f * (red[0] / (float)((long long)N_TOK * DIM));
    }
}

// ---------------------------------------------------------------------------
extern "C" void kernel_launch(void* const* d_in, const int* in_sizes, int n_in,
                              void* d_out, int out_size) {
    const float* x = (const float*)d_in[0];
    const float* w = (const float*)d_in[1];
    if (n_in >= 2 && in_sizes[0] < in_sizes[1]) {
        x = (const float*)d_in[1];
        w = (const float*)d_in[0];
    }

    float* out = (float*)d_out;
    const long long ND = (long long)N_TOK * DIM;
    float* out_loss = out;
    float* out_q    = out + 1;
    float* out_perp = out + 1 + ND;
    float* out_idx  = out + 2 + ND;

    vq_prep<<<8, 128>>>(w);
    vq_main<<<NBLK, TPB>>>(x, out_q, out_idx, out_loss, out_perp);
}